// round 1
// baseline (speedup 1.0000x reference)
#include <cuda_runtime.h>
#include <math.h>

#define Bn   8
#define Cn   64
#define Nn   4096
#define On   64
#define KNN  20
#define SLOPE 0.2f
#define EPSC  1e-5f

// ---------------- device scratch (static, no allocations) ----------------
__device__ float g_xx[Bn * Nn];                 // squared norms
__device__ int   g_idx[Bn * Nn * KNN];          // knn indices
__device__ float g_u[Bn * Nn * On];             // x . W1^T
__device__ float g_v[Bn * Nn * On];             // x . (W2-W1)^T
__device__ float g_sel[Bn * Nn * On];           // max (or min) raw y over k
__device__ float g_sum[On];
__device__ float g_sumsq[On];
__device__ float g_cA[On];
__device__ float g_cB[On];

// ---------------- K1: squared norms ----------------
__global__ void xx_kernel(const float* __restrict__ x) {
    int i = blockIdx.x * 256 + threadIdx.x;       // 0..B*N-1
    int b = i >> 12;
    int n = i & (Nn - 1);
    const float* xp = x + b * Cn * Nn + n;
    float s = 0.f;
#pragma unroll
    for (int c = 0; c < Cn; ++c) {
        float v = xp[c * Nn];
        s = fmaf(v, v, s);
    }
    g_xx[i] = s;
}

// ---------------- K2: fused distance GEMM + top-K ----------------
// block: 256 threads. 16 rows (n) per block, 16 threads per row.
// m-tiles of 128 columns; each thread handles 8 contiguous columns.
#define ROWS 16
#define TPR  16
#define MT   128

__global__ void __launch_bounds__(256, 3) knn_kernel(const float* __restrict__ x) {
    __shared__ float s_xc[Cn][ROWS];
    __shared__ float s_xxm[MT];
    __shared__ union SmemU {
        float xm[Cn][MT];                                   // 32 KB
        struct { float mval[ROWS][TPR * KNN];               // 20 KB
                 int   midx[ROWS][TPR * KNN]; } mg;         // 20 KB
    } smu;

    int t    = threadIdx.x;
    int r    = t / TPR;           // row within block (0..15)
    int cs   = t % TPR;           // column-subgroup (0..15)
    int b    = blockIdx.x / (Nn / ROWS);
    int n0   = (blockIdx.x % (Nn / ROWS)) * ROWS;
    const float* xb = x + b * Cn * Nn;

    // load center tile [C][ROWS]
    for (int i = t; i < Cn * ROWS; i += 256) {
        int c = i / ROWS, rr = i % ROWS;
        s_xc[c][rr] = xb[c * Nn + n0 + rr];
    }

    float vals[KNN];
    int   idxs[KNN];
#pragma unroll
    for (int j = 0; j < KNN; ++j) { vals[j] = -INFINITY; idxs[j] = -1; }

    __syncthreads();

    int colbase = cs * 8;
    for (int m0 = 0; m0 < Nn; m0 += MT) {
        // load candidate tile [C][MT] + xx tile
        for (int i = t; i < Cn * MT; i += 256) {
            int c = i / MT, mm = i % MT;
            smu.xm[c][mm] = xb[c * Nn + m0 + mm];
        }
        if (t < MT) s_xxm[t] = g_xx[b * Nn + m0 + t];
        __syncthreads();

        float acc[8];
#pragma unroll
        for (int j = 0; j < 8; ++j) acc[j] = 0.f;

#pragma unroll 8
        for (int c = 0; c < Cn; ++c) {
            float xcv = s_xc[c][r];
            float4 a0 = *reinterpret_cast<const float4*>(&smu.xm[c][colbase]);
            float4 a1 = *reinterpret_cast<const float4*>(&smu.xm[c][colbase + 4]);
            acc[0] = fmaf(xcv, a0.x, acc[0]);
            acc[1] = fmaf(xcv, a0.y, acc[1]);
            acc[2] = fmaf(xcv, a0.z, acc[2]);
            acc[3] = fmaf(xcv, a0.w, acc[3]);
            acc[4] = fmaf(xcv, a1.x, acc[4]);
            acc[5] = fmaf(xcv, a1.y, acc[5]);
            acc[6] = fmaf(xcv, a1.z, acc[6]);
            acc[7] = fmaf(xcv, a1.w, acc[7]);
        }

#pragma unroll
        for (int j = 0; j < 8; ++j) {
            int m = m0 + colbase + j;
            float sc = fmaf(2.f, acc[j], -s_xxm[colbase + j]);
            if (sc > vals[KNN - 1]) {
                vals[KNN - 1] = sc; idxs[KNN - 1] = m;
#pragma unroll
                for (int q = KNN - 1; q > 0; --q) {
                    if (vals[q] > vals[q - 1]) {
                        float tv = vals[q]; vals[q] = vals[q - 1]; vals[q - 1] = tv;
                        int   ti = idxs[q]; idxs[q] = idxs[q - 1]; idxs[q - 1] = ti;
                    }
                }
            }
        }
        __syncthreads();
    }

    // write per-thread sorted lists, then 16-way merge per row
#pragma unroll
    for (int j = 0; j < KNN; ++j) {
        smu.mg.mval[r][cs * KNN + j] = vals[j];
        smu.mg.midx[r][cs * KNN + j] = idxs[j];
    }
    __syncthreads();

    if (cs == 0) {
        int head[TPR];
#pragma unroll
        for (int s = 0; s < TPR; ++s) head[s] = 0;
        int obase = (b * Nn + n0 + r) * KNN;
        for (int kk = 0; kk < KNN; ++kk) {
            float bv = -INFINITY; int bi = 0x7fffffff; int bs = 0;
            for (int s = 0; s < TPR; ++s) {
                int h = head[s];
                if (h < KNN) {
                    float v  = smu.mg.mval[r][s * KNN + h];
                    int   im = smu.mg.midx[r][s * KNN + h];
                    if (v > bv || (v == bv && im < bi)) { bv = v; bi = im; bs = s; }
                }
            }
            g_idx[obase + kk] = bi;
            head[bs]++;
        }
    }
}

// ---------------- K3: projections u = x.W1^T, v = x.(W2-W1)^T ----------------
__global__ void proj_kernel(const float* __restrict__ x, const float* __restrict__ W) {
    __shared__ float s_w1[Cn][On];
    __shared__ float s_wd[Cn][On];
    __shared__ float s_x[Cn][32];

    int t = threadIdx.x;
    for (int i = t; i < On * Cn; i += 256) {
        int o = i / Cn, c = i % Cn;
        float w1 = W[o * (2 * Cn) + c];
        float w2 = W[o * (2 * Cn) + Cn + c];
        s_w1[c][o] = w1;
        s_wd[c][o] = w2 - w1;
    }
    int b  = blockIdx.x / (Nn / 32);
    int n0 = (blockIdx.x % (Nn / 32)) * 32;
    for (int i = t; i < Cn * 32; i += 256) {
        int c = i / 32, p = i % 32;
        s_x[c][p] = x[b * Cn * Nn + c * Nn + n0 + p];
    }
    __syncthreads();

    int warp = t >> 5, lane = t & 31;
    int p0 = warp * 4;
    float au0[4] = {0,0,0,0}, au1[4] = {0,0,0,0};
    float av0[4] = {0,0,0,0}, av1[4] = {0,0,0,0};

#pragma unroll 8
    for (int c = 0; c < Cn; ++c) {
        float w1l = s_w1[c][lane], w1h = s_w1[c][lane + 32];
        float wdl = s_wd[c][lane], wdh = s_wd[c][lane + 32];
#pragma unroll
        for (int pp = 0; pp < 4; ++pp) {
            float xv = s_x[c][p0 + pp];
            au0[pp] = fmaf(xv, w1l, au0[pp]);
            au1[pp] = fmaf(xv, w1h, au1[pp]);
            av0[pp] = fmaf(xv, wdl, av0[pp]);
            av1[pp] = fmaf(xv, wdh, av1[pp]);
        }
    }
#pragma unroll
    for (int pp = 0; pp < 4; ++pp) {
        int pt = b * Nn + n0 + p0 + pp;
        g_u[pt * On + lane]      = au0[pp];
        g_u[pt * On + 32 + lane] = au1[pp];
        g_v[pt * On + lane]      = av0[pp];
        g_v[pt * On + 32 + lane] = av1[pp];
    }
}

// ---------------- K0: zero stats ----------------
__global__ void zero_kernel() {
    int t = threadIdx.x;
    if (t < On) { g_sum[t] = 0.f; g_sumsq[t] = 0.f; }
}

// ---------------- K4: gather, max/min over k, stats partials ----------------
__global__ void maxstats_kernel(const float* __restrict__ gamma) {
    __shared__ float ssum[8][On];
    __shared__ float ssq[8][On];
    int warp = threadIdx.x >> 5, lane = threadIdx.x & 31;
    int pt = blockIdx.x * 8 + warp;
    int b = pt >> 12;

    const float* vp = g_v + pt * On;
    float v0 = vp[lane], v1 = vp[lane + 32];
    float mx0 = -INFINITY, mx1 = -INFINITY, mn0 = INFINITY, mn1 = INFINITY;
    float s0 = 0.f, s1 = 0.f, q0 = 0.f, q1 = 0.f;
    const int* ip = g_idx + pt * KNN;

#pragma unroll
    for (int k = 0; k < KNN; ++k) {
        int m = ip[k];
        const float* up = g_u + ((b << 12) + m) * On;
        float y0 = up[lane] + v0;
        float y1 = up[lane + 32] + v1;
        mx0 = fmaxf(mx0, y0); mn0 = fminf(mn0, y0);
        mx1 = fmaxf(mx1, y1); mn1 = fminf(mn1, y1);
        s0 += y0; q0 = fmaf(y0, y0, q0);
        s1 += y1; q1 = fmaf(y1, y1, q1);
    }
    float g0 = gamma[lane], g1 = gamma[lane + 32];
    g_sel[pt * On + lane]      = (g0 >= 0.f) ? mx0 : mn0;
    g_sel[pt * On + 32 + lane] = (g1 >= 0.f) ? mx1 : mn1;

    ssum[warp][lane] = s0; ssum[warp][lane + 32] = s1;
    ssq[warp][lane]  = q0; ssq[warp][lane + 32]  = q1;
    __syncthreads();
    if (threadIdx.x < On) {
        float ts = 0.f, tq = 0.f;
#pragma unroll
        for (int w = 0; w < 8; ++w) { ts += ssum[w][threadIdx.x]; tq += ssq[w][threadIdx.x]; }
        atomicAdd(&g_sum[threadIdx.x], ts);
        atomicAdd(&g_sumsq[threadIdx.x], tq);
    }
}

// ---------------- K6: BN coefficients ----------------
__global__ void bnfinal_kernel(const float* __restrict__ gamma, const float* __restrict__ beta) {
    int o = threadIdx.x;
    if (o < On) {
        const float M = (float)(Bn * Nn * KNN);
        float mean = g_sum[o] / M;
        float var  = g_sumsq[o] / M - mean * mean;
        var = fmaxf(var, 0.f);
        float a = gamma[o] * rsqrtf(var + EPSC);
        g_cA[o] = a;
        g_cB[o] = beta[o] - mean * a;
    }
}

// ---------------- K7: BN apply + LeakyReLU + transpose to (B,O,N) ----------------
__global__ void finalize_kernel(float* __restrict__ out) {
    __shared__ float tile[32][On + 1];
    __shared__ float sA[On], sB[On];
    int t = threadIdx.x;
    int b  = blockIdx.x / (Nn / 32);
    int n0 = (blockIdx.x % (Nn / 32)) * 32;
    if (t < On) { sA[t] = g_cA[t]; sB[t] = g_cB[t]; }
    for (int i = t; i < 32 * On; i += 256) {
        int nl = i / On, o = i % On;
        tile[nl][o] = g_sel[(b * Nn + n0) * On + i];
    }
    __syncthreads();
    for (int i = t; i < 32 * On; i += 256) {
        int o = i / 32, nl = i % 32;
        float y = tile[nl][o];
        float val = fmaf(sA[o], y, sB[o]);
        out[b * On * Nn + o * Nn + n0 + nl] = (val >= 0.f) ? val : SLOPE * val;
    }
}

// ---------------- launch ----------------
extern "C" void kernel_launch(void* const* d_in, const int* in_sizes, int n_in,
                              void* d_out, int out_size) {
    const float* x     = (const float*)d_in[0];
    const float* W     = (const float*)d_in[1];
    const float* gamma = (const float*)d_in[2];
    const float* beta  = (const float*)d_in[3];
    float* out = (float*)d_out;

    xx_kernel<<<(Bn * Nn) / 256, 256>>>(x);
    knn_kernel<<<Bn * (Nn / ROWS), 256>>>(x);
    proj_kernel<<<Bn * (Nn / 32), 256>>>(x, W);
    zero_kernel<<<1, 64>>>();
    maxstats_kernel<<<(Bn * Nn) / 8, 256>>>(gamma);
    bnfinal_kernel<<<1, 64>>>(gamma, beta);
    finalize_kernel<<<Bn * (Nn / 32), 256>>>(out);
}

// round 2
// speedup vs baseline: 2.1951x; 2.1951x over previous
#include <cuda_runtime.h>
#include <math.h>

#define Bn   8
#define Cn   64
#define Nn   4096
#define On   64
#define KNN  20
#define SLOPE 0.2f
#define EPSC  1e-5f

// ---------------- device scratch ----------------
__device__ float g_xx[Bn * Nn];
__device__ int   g_idx[Bn * Nn * KNN];
__device__ float g_u[Bn * Nn * On];
__device__ float g_v[Bn * Nn * On];
__device__ float g_sel[Bn * Nn * On];
__device__ float g_sum[On];
__device__ float g_sumsq[On];
__device__ float g_cA[On];
__device__ float g_cB[On];

// ---------------- K1: squared norms ----------------
__global__ void xx_kernel(const float* __restrict__ x) {
    int i = blockIdx.x * 256 + threadIdx.x;
    int b = i >> 12;
    int n = i & (Nn - 1);
    const float* xp = x + b * Cn * Nn + n;
    float s = 0.f;
#pragma unroll
    for (int c = 0; c < Cn; ++c) {
        float v = xp[c * Nn];
        s = fmaf(v, v, s);
    }
    g_xx[i] = s;
}

// ---------------- K2: register-tiled distance GEMM + staged top-K ----------------
// Block: 256 threads, 64 rows (n), sweeps all 4096 cols in 128-col tiles.
// Compute: 16x16 thread grid, 4 rows x 8 cols micro-tile per thread.
// Scores staged owner-major skewed: s_sc[owner*33 + slot], owner = row*4 + quarter.
#define RT 64
#define MTile 128

#define OFF_XC  0                   // 64*64 f   = 16384 B
#define OFF_XXM 16384               // 128 f     = 512 B
#define OFF_XM  16896               // 64*128 f  = 32768 B
#define OFF_SC  49664               // 256*33 f  = 33792 B
#define OFF_MV  0                   // 256*20 f  = 20480 B (reuses xc area post-loop)
#define OFF_MI  20480               // 256*20 i  = 20480 B (reuses xm area post-loop)
#define SMEM_KNN 83456

__global__ void __launch_bounds__(256, 2) knn_kernel(const float* __restrict__ x) {
    extern __shared__ char smraw[];
    float* s_xc  = (float*)(smraw + OFF_XC);
    float* s_xxm = (float*)(smraw + OFF_XXM);
    float* s_xm  = (float*)(smraw + OFF_XM);
    float* s_sc  = (float*)(smraw + OFF_SC);
    float* s_mv  = (float*)(smraw + OFF_MV);
    int*   s_mi  = (int*)  (smraw + OFF_MI);

    int t  = threadIdx.x;
    int b  = blockIdx.x >> 6;
    int n0 = (blockIdx.x & 63) * RT;
    const float* xb = x + b * Cn * Nn;

    // persistent center tile [c][row]
    for (int i = t; i < Cn * RT; i += 256) {
        int c = i >> 6, r = i & 63;
        s_xc[c * RT + r] = xb[c * Nn + n0 + r];
    }

    int cg = t & 15, rg = t >> 4;
    int row0 = rg * 4, col0 = cg * 8;
    int q8 = cg >> 2, c3 = cg & 3;

    float vals[KNN];
    int   idxs[KNN];
#pragma unroll
    for (int j = 0; j < KNN; ++j) { vals[j] = -INFINITY; idxs[j] = 0x7fffffff; }

    int sbase = t * 33;          // this thread's owner slot
    int mcol0 = (t & 3) * 32;    // quarter column offset

    for (int m0 = 0; m0 < Nn; m0 += MTile) {
        // load candidate tile + norms
        for (int i = t; i < Cn * MTile; i += 256) {
            int c = i >> 7, m = i & 127;
            s_xm[c * MTile + m] = xb[c * Nn + m0 + m];
        }
        if (t < MTile) s_xxm[t] = g_xx[b * Nn + m0 + t];
        __syncthreads();

        float acc[4][8];
#pragma unroll
        for (int rr = 0; rr < 4; ++rr)
#pragma unroll
            for (int j = 0; j < 8; ++j) acc[rr][j] = 0.f;

#pragma unroll 8
        for (int c = 0; c < Cn; ++c) {
            float4 xr = *(const float4*)(s_xc + c * RT + row0);
            float4 a0 = *(const float4*)(s_xm + c * MTile + col0);
            float4 a1 = *(const float4*)(s_xm + c * MTile + col0 + 4);
            float rv[4] = {xr.x, xr.y, xr.z, xr.w};
            float av[8] = {a0.x, a0.y, a0.z, a0.w, a1.x, a1.y, a1.z, a1.w};
#pragma unroll
            for (int rr = 0; rr < 4; ++rr)
#pragma unroll
                for (int j = 0; j < 8; ++j)
                    acc[rr][j] = fmaf(rv[rr], av[j], acc[rr][j]);
        }

        // stage scores: owner = (row)*4 + quarter, slot = c3*8 + j
#pragma unroll
        for (int rr = 0; rr < 4; ++rr) {
            int ow = (row0 + rr) * 4 + q8;
#pragma unroll
            for (int j = 0; j < 8; ++j) {
                s_sc[ow * 33 + c3 * 8 + j] =
                    fmaf(2.f, acc[rr][j], -s_xxm[col0 + j]);
            }
        }
        __syncthreads();

        // top-k scan: 32 contiguous (skewed) scores, conflict-free
        int mbase = m0 + mcol0;
#pragma unroll 4
        for (int j = 0; j < 32; ++j) {
            float sc = s_sc[sbase + j];
            if (sc > vals[KNN - 1]) {
                vals[KNN - 1] = sc; idxs[KNN - 1] = mbase + j;
#pragma unroll
                for (int qq = KNN - 1; qq > 0; --qq) {
                    bool sw = vals[qq] > vals[qq - 1];
                    float tv = sw ? vals[qq - 1] : vals[qq];
                    float tu = sw ? vals[qq]     : vals[qq - 1];
                    int   ti = sw ? idxs[qq - 1] : idxs[qq];
                    int   tj = sw ? idxs[qq]     : idxs[qq - 1];
                    vals[qq] = tv; vals[qq - 1] = tu;
                    idxs[qq] = ti; idxs[qq - 1] = tj;
                }
            }
        }
        __syncthreads();
    }

    // dump per-thread sorted lists (reuses xc/xm smem; disjoint from s_sc)
#pragma unroll
    for (int j = 0; j < KNN; ++j) {
        s_mv[t * KNN + j] = vals[j];
        s_mi[t * KNN + j] = idxs[j];
    }
    __syncthreads();

    // 4-way merge per row
    if (t < RT) {
        int head[4] = {0, 0, 0, 0};
        int lb = t * 4 * KNN;
        int obase = (b * Nn + n0 + t) * KNN;
        for (int kk = 0; kk < KNN; ++kk) {
            float bv = -INFINITY; int bi = 0x7fffffff; int bs = 0;
#pragma unroll
            for (int s = 0; s < 4; ++s) {
                int h = head[s];
                if (h < KNN) {
                    float v  = s_mv[lb + s * KNN + h];
                    int   im = s_mi[lb + s * KNN + h];
                    if (v > bv || (v == bv && im < bi)) { bv = v; bi = im; bs = s; }
                }
            }
            g_idx[obase + kk] = bi;
            head[bs]++;
        }
    }
}

// ---------------- K3: projections ----------------
__global__ void proj_kernel(const float* __restrict__ x, const float* __restrict__ W) {
    __shared__ float s_w1[Cn][On];
    __shared__ float s_wd[Cn][On];
    __shared__ float s_x[Cn][32];

    int t = threadIdx.x;
    for (int i = t; i < On * Cn; i += 256) {
        int o = i / Cn, c = i % Cn;
        float w1 = W[o * (2 * Cn) + c];
        float w2 = W[o * (2 * Cn) + Cn + c];
        s_w1[c][o] = w1;
        s_wd[c][o] = w2 - w1;
    }
    int b  = blockIdx.x / (Nn / 32);
    int n0 = (blockIdx.x % (Nn / 32)) * 32;
    for (int i = t; i < Cn * 32; i += 256) {
        int c = i / 32, p = i % 32;
        s_x[c][p] = x[b * Cn * Nn + c * Nn + n0 + p];
    }
    __syncthreads();

    int warp = t >> 5, lane = t & 31;
    int p0 = warp * 4;
    float au0[4] = {0,0,0,0}, au1[4] = {0,0,0,0};
    float av0[4] = {0,0,0,0}, av1[4] = {0,0,0,0};

#pragma unroll 8
    for (int c = 0; c < Cn; ++c) {
        float w1l = s_w1[c][lane], w1h = s_w1[c][lane + 32];
        float wdl = s_wd[c][lane], wdh = s_wd[c][lane + 32];
#pragma unroll
        for (int pp = 0; pp < 4; ++pp) {
            float xv = s_x[c][p0 + pp];
            au0[pp] = fmaf(xv, w1l, au0[pp]);
            au1[pp] = fmaf(xv, w1h, au1[pp]);
            av0[pp] = fmaf(xv, wdl, av0[pp]);
            av1[pp] = fmaf(xv, wdh, av1[pp]);
        }
    }
#pragma unroll
    for (int pp = 0; pp < 4; ++pp) {
        int pt = b * Nn + n0 + p0 + pp;
        g_u[pt * On + lane]      = au0[pp];
        g_u[pt * On + 32 + lane] = au1[pp];
        g_v[pt * On + lane]      = av0[pp];
        g_v[pt * On + 32 + lane] = av1[pp];
    }
}

// ---------------- K0: zero stats ----------------
__global__ void zero_kernel() {
    int t = threadIdx.x;
    if (t < On) { g_sum[t] = 0.f; g_sumsq[t] = 0.f; }
}

// ---------------- K4: gather, max/min over k, stats ----------------
__global__ void maxstats_kernel(const float* __restrict__ gamma) {
    __shared__ float ssum[8][On];
    __shared__ float ssq[8][On];
    int warp = threadIdx.x >> 5, lane = threadIdx.x & 31;
    int pt = blockIdx.x * 8 + warp;
    int b = pt >> 12;

    const float* vp = g_v + pt * On;
    float v0 = vp[lane], v1 = vp[lane + 32];
    float mx0 = -INFINITY, mx1 = -INFINITY, mn0 = INFINITY, mn1 = INFINITY;
    float s0 = 0.f, s1 = 0.f, q0 = 0.f, q1 = 0.f;
    const int* ip = g_idx + pt * KNN;

#pragma unroll
    for (int k = 0; k < KNN; ++k) {
        int m = ip[k];
        const float* up = g_u + ((b << 12) + m) * On;
        float y0 = up[lane] + v0;
        float y1 = up[lane + 32] + v1;
        mx0 = fmaxf(mx0, y0); mn0 = fminf(mn0, y0);
        mx1 = fmaxf(mx1, y1); mn1 = fminf(mn1, y1);
        s0 += y0; q0 = fmaf(y0, y0, q0);
        s1 += y1; q1 = fmaf(y1, y1, q1);
    }
    float g0 = gamma[lane], g1 = gamma[lane + 32];
    g_sel[pt * On + lane]      = (g0 >= 0.f) ? mx0 : mn0;
    g_sel[pt * On + 32 + lane] = (g1 >= 0.f) ? mx1 : mn1;

    ssum[warp][lane] = s0; ssum[warp][lane + 32] = s1;
    ssq[warp][lane]  = q0; ssq[warp][lane + 32]  = q1;
    __syncthreads();
    if (threadIdx.x < On) {
        float ts = 0.f, tq = 0.f;
#pragma unroll
        for (int w = 0; w < 8; ++w) { ts += ssum[w][threadIdx.x]; tq += ssq[w][threadIdx.x]; }
        atomicAdd(&g_sum[threadIdx.x], ts);
        atomicAdd(&g_sumsq[threadIdx.x], tq);
    }
}

// ---------------- K6: BN coefficients ----------------
__global__ void bnfinal_kernel(const float* __restrict__ gamma, const float* __restrict__ beta) {
    int o = threadIdx.x;
    if (o < On) {
        const float M = (float)(Bn * Nn * KNN);
        float mean = g_sum[o] / M;
        float var  = g_sumsq[o] / M - mean * mean;
        var = fmaxf(var, 0.f);
        float a = gamma[o] * rsqrtf(var + EPSC);
        g_cA[o] = a;
        g_cB[o] = beta[o] - mean * a;
    }
}

// ---------------- K7: finalize + transpose ----------------
__global__ void finalize_kernel(float* __restrict__ out) {
    __shared__ float tile[32][On + 1];
    __shared__ float sA[On], sB[On];
    int t = threadIdx.x;
    int b  = blockIdx.x / (Nn / 32);
    int n0 = (blockIdx.x % (Nn / 32)) * 32;
    if (t < On) { sA[t] = g_cA[t]; sB[t] = g_cB[t]; }
    for (int i = t; i < 32 * On; i += 256) {
        int nl = i / On, o = i % On;
        tile[nl][o] = g_sel[(b * Nn + n0) * On + i];
    }
    __syncthreads();
    for (int i = t; i < 32 * On; i += 256) {
        int o = i / 32, nl = i % 32;
        float y = tile[nl][o];
        float val = fmaf(sA[o], y, sB[o]);
        out[b * On * Nn + o * Nn + n0 + nl] = (val >= 0.f) ? val : SLOPE * val;
    }
}

// ---------------- launch ----------------
extern "C" void kernel_launch(void* const* d_in, const int* in_sizes, int n_in,
                              void* d_out, int out_size) {
    const float* x     = (const float*)d_in[0];
    const float* W     = (const float*)d_in[1];
    const float* gamma = (const float*)d_in[2];
    const float* beta  = (const float*)d_in[3];
    float* out = (float*)d_out;

    cudaFuncSetAttribute(knn_kernel, cudaFuncAttributeMaxDynamicSharedMemorySize, SMEM_KNN);

    xx_kernel<<<(Bn * Nn) / 256, 256>>>(x);
    knn_kernel<<<Bn * (Nn / RT), 256, SMEM_KNN>>>(x);
    proj_kernel<<<Bn * (Nn / 32), 256>>>(x, W);
    zero_kernel<<<1, 64>>>();
    maxstats_kernel<<<(Bn * Nn) / 8, 256>>>(gamma);
    bnfinal_kernel<<<1, 64>>>(gamma, beta);
    finalize_kernel<<<Bn * (Nn / 32), 256>>>(out);
}